// round 4
// baseline (speedup 1.0000x reference)
#include <cuda_runtime.h>
#include <math.h>

#define BINSIZE      200
#define BINWIDTH     500
#define N_CLUSTERS   20
#define N_ROI_MAX    200
#define N_CELLS_MAX  100352   // 100000 rounded up to 16B multiple
#define SMEM_BYTES   100352

// Precomputed log-density table: [n_roi, n_clusters, BINWIDTH]
__device__ float g_heights[N_ROI_MAX * N_CLUSTERS * BINWIDTH];
// labels compacted to uint8
__device__ unsigned char g_labels8[N_CELLS_MAX];

// ---------------------------------------------------------------------------
// Kernel 1 (fused): heights build (warp per row) + label int32->uint8 pack.
// ---------------------------------------------------------------------------
__global__ void __launch_bounds__(256) build_kernel(
    const float* __restrict__ baseline,
    const float* __restrict__ delta,
    const int*   __restrict__ regions_oi,
    const int*   __restrict__ labels,
    int n_rows, int n_clusters, int rowBlocks, int n_cells)
{
    if ((int)blockIdx.x < rowBlocks) {
        const int warp = (int)blockIdx.x * 8 + ((int)threadIdx.x >> 5);
        if (warp >= n_rows) return;
        const int lane = threadIdx.x & 31;
        const int roi = warp / n_clusters;
        const int cl  = warp - roi * n_clusters;
        const int region = regions_oi[roi];

        const float4* __restrict__ b4 = (const float4*)(baseline + (long long)region * BINWIDTH);
        const float4* __restrict__ d4 = (const float4*)(delta + ((long long)region * n_clusters + cl) * BINWIDTH);

        float4 v[4];
        float m = -INFINITY;
        #pragma unroll
        for (int it = 0; it < 4; it++) {
            const int idx = lane + it * 32;
            if (idx < 125) {
                float4 a = b4[idx];
                float4 d = d4[idx];
                v[it].x = a.x + d.x; v[it].y = a.y + d.y;
                v[it].z = a.z + d.z; v[it].w = a.w + d.w;
                m = fmaxf(m, fmaxf(fmaxf(v[it].x, v[it].y), fmaxf(v[it].z, v[it].w)));
            }
        }
        #pragma unroll
        for (int o = 16; o > 0; o >>= 1)
            m = fmaxf(m, __shfl_xor_sync(0xffffffffu, m, o));

        float s = 0.0f;
        #pragma unroll
        for (int it = 0; it < 4; it++) {
            const int idx = lane + it * 32;
            if (idx < 125) {
                s += __expf(v[it].x - m) + __expf(v[it].y - m)
                   + __expf(v[it].z - m) + __expf(v[it].w - m);
            }
        }
        #pragma unroll
        for (int o = 16; o > 0; o >>= 1)
            s += __shfl_xor_sync(0xffffffffu, s, o);

        const float sub = m + __logf(s) + logf((float)BINSIZE);

        float4* __restrict__ o4 = (float4*)(g_heights + (long long)warp * BINWIDTH);
        #pragma unroll
        for (int it = 0; it < 4; it++) {
            const int idx = lane + it * 32;
            if (idx < 125) {
                float4 h;
                h.x = v[it].x - sub; h.y = v[it].y - sub;
                h.z = v[it].z - sub; h.w = v[it].w - sub;
                o4[idx] = h;
            }
        }
    } else {
        const int b = (int)blockIdx.x - rowBlocks;
        const int t = b * 256 + (int)threadIdx.x;
        const int i0 = t * 4;
        if (i0 + 4 <= n_cells) {
            const int4 l = ((const int4*)labels)[t];
            uchar4 p;
            p.x = (unsigned char)l.x; p.y = (unsigned char)l.y;
            p.z = (unsigned char)l.z; p.w = (unsigned char)l.w;
            ((uchar4*)g_labels8)[t] = p;
        } else {
            for (int i = i0; i < n_cells; i++)
                g_labels8[i] = (unsigned char)labels[i];
        }
    }
}

// ---------------------------------------------------------------------------
// Kernel 2: gather with labels in shared memory. 1024 threads/block,
// 2 blocks/SM (200KB smem/SM) => 64 warps/SM. Each thread handles 8
// fragments in two batches of 4 (keeps regs <= 32 for full occupancy).
// Single pass: grid covers all groups.
// ---------------------------------------------------------------------------
__global__ void __launch_bounds__(1024, 2) gather_smem_kernel(
    const int*   __restrict__ coords,      // [n, 2]
    const int*   __restrict__ lrix,        // [n]
    const int*   __restrict__ lcix,        // [n]
    const float* __restrict__ inside,      // [1]
    float*       __restrict__ out,         // [n, 2]
    int n, int n_cells, int n_groups)
{
    extern __shared__ unsigned char s_labels[];

    // Cooperative fill of the label table.
    {
        const int nvec = (n_cells + 15) >> 4;
        const int4* src = (const int4*)g_labels8;
        int4* dst = (int4*)s_labels;
        for (int i = threadIdx.x; i < nvec; i += blockDim.x)
            dst[i] = src[i];
    }
    __syncthreads();

    const int g = blockIdx.x * blockDim.x + threadIdx.x;
    if (g >= n_groups) return;

    const float x    = inside[0];
    const float l1p  = log1pf(expf(-x));
    const float lpIn  = -l1p     - logf((float)BINWIDTH);
    const float lpOut = -x - l1p - logf((float)(100000 - BINWIDTH));

    const int i0 = g * 8;
    if (i0 + 8 <= n) {
        #pragma unroll
        for (int half = 0; half < 2; half++) {
            // 4 fragments per batch, fully self-contained
            const int4 c0 = ((const int4*)coords)[g * 4 + half * 2 + 0];
            const int4 c1 = ((const int4*)coords)[g * 4 + half * 2 + 1];
            const int4 rr = ((const int4*)lrix)[g * 2 + half];
            const int4 qq = ((const int4*)lcix)[g * 2 + half];

            const int lab0 = s_labels[qq.x];
            const int lab1 = s_labels[qq.y];
            const int lab2 = s_labels[qq.z];
            const int lab3 = s_labels[qq.w];

            const int bl0 = c0.x / BINSIZE, br0 = c0.y / BINSIZE;
            const int bl1 = c0.z / BINSIZE, br1 = c0.w / BINSIZE;
            const int bl2 = c1.x / BINSIZE, br2 = c1.y / BINSIZE;
            const int bl3 = c1.z / BINSIZE, br3 = c1.w / BINSIZE;

            const float L0 = g_heights[(rr.x * N_CLUSTERS + lab0) * BINWIDTH + bl0];
            const float L1 = g_heights[(rr.y * N_CLUSTERS + lab1) * BINWIDTH + bl1];
            const float L2 = g_heights[(rr.z * N_CLUSTERS + lab2) * BINWIDTH + bl2];
            const float L3 = g_heights[(rr.w * N_CLUSTERS + lab3) * BINWIDTH + bl3];

            float4 o0, o1;
            o0.x = L0; o0.y = (bl0 == br0) ? lpIn : lpOut;
            o0.z = L1; o0.w = (bl1 == br1) ? lpIn : lpOut;
            o1.x = L2; o1.y = (bl2 == br2) ? lpIn : lpOut;
            o1.z = L3; o1.w = (bl3 == br3) ? lpIn : lpOut;
            ((float4*)out)[g * 4 + half * 2 + 0] = o0;
            ((float4*)out)[g * 4 + half * 2 + 1] = o1;
        }
    } else {
        for (int i = i0; i < n; i++) {
            const int cx = coords[i * 2 + 0];
            const int cy = coords[i * 2 + 1];
            const int bl = cx / BINSIZE, br = cy / BINSIZE;
            const int lab = s_labels[lcix[i]];
            const int rg = lrix[i];
            out[i * 2 + 0] = g_heights[(rg * N_CLUSTERS + lab) * BINWIDTH + bl];
            out[i * 2 + 1] = (bl == br) ? lpIn : lpOut;
        }
    }
}

// Fallback (labels table too big for smem).
__global__ void __launch_bounds__(256) gather_global_kernel(
    const int*   __restrict__ coords,
    const int*   __restrict__ lrix,
    const int*   __restrict__ lcix,
    const float* __restrict__ inside,
    float*       __restrict__ out,
    int n)
{
    const int tid = blockIdx.x * blockDim.x + threadIdx.x;
    const int i0  = tid * 8;
    if (i0 >= n) return;

    const float x    = inside[0];
    const float l1p  = log1pf(expf(-x));
    const float lpIn  = -l1p     - logf((float)BINWIDTH);
    const float lpOut = -x - l1p - logf((float)(100000 - BINWIDTH));

    for (int i = i0; i < n && i < i0 + 8; i++) {
        const int cx = coords[i * 2 + 0];
        const int cy = coords[i * 2 + 1];
        const int bl = cx / BINSIZE, br = cy / BINSIZE;
        const int lab = g_labels8[lcix[i]];
        const int rg = lrix[i];
        out[i * 2 + 0] = g_heights[(rg * N_CLUSTERS + lab) * BINWIDTH + bl];
        out[i * 2 + 1] = (bl == br) ? lpIn : lpOut;
    }
}

// ---------------------------------------------------------------------------
extern "C" void kernel_launch(void* const* d_in, const int* in_sizes, int n_in,
                              void* d_out, int out_size)
{
    const float* baseline = (const float*)d_in[0];
    const float* delta    = (const float*)d_in[1];
    const float* inside   = (const float*)d_in[2];
    const int*   regions  = (const int*)d_in[3];
    const int*   coords   = (const int*)d_in[4];
    const int*   lrix     = (const int*)d_in[5];
    const int*   lcix     = (const int*)d_in[6];
    const int*   labels   = (const int*)d_in[7];
    float*       out      = (float*)d_out;

    const int n_roi      = in_sizes[3];
    const int n          = in_sizes[5];
    const int n_cells    = in_sizes[7];
    const int n_regions  = in_sizes[0] / BINWIDTH;
    const int n_clusters = (n_regions > 0) ? (in_sizes[1] / (n_regions * BINWIDTH)) : N_CLUSTERS;

    const int n_rows    = n_roi * n_clusters;
    const int rowBlocks = (n_rows + 7) / 8;
    const int packBlocks = (n_cells + 1023) / 1024;
    build_kernel<<<rowBlocks + packBlocks, 256>>>(
        baseline, delta, regions, labels, n_rows, n_clusters, rowBlocks, n_cells);

    const int n_groups = (n + 7) / 8;
    if (n_cells <= N_CELLS_MAX) {
        static bool attr_set = false;
        if (!attr_set) {
            cudaFuncSetAttribute(gather_smem_kernel,
                                 cudaFuncAttributeMaxDynamicSharedMemorySize, SMEM_BYTES);
            attr_set = true;
        }
        const int blocks = (n_groups + 1023) / 1024;   // one group per thread
        gather_smem_kernel<<<blocks, 1024, SMEM_BYTES>>>(
            coords, lrix, lcix, inside, out, n, n_cells, n_groups);
    } else {
        const int blocks = (n_groups + 255) / 256;
        gather_global_kernel<<<blocks, 256>>>(coords, lrix, lcix, inside, out, n);
    }
}

// round 6
// speedup vs baseline: 1.5845x; 1.5845x over previous
#include <cuda_runtime.h>
#include <math.h>

#define BINSIZE      200
#define BINWIDTH     500
#define N_CLUSTERS   20
#define N_ROI_MAX    200
#define N_CELLS_MAX  100352   // 100000 rounded up to 16B multiple

// Precomputed log-density table: [n_roi, n_clusters, BINWIDTH]
__device__ float g_heights[N_ROI_MAX * N_CLUSTERS * BINWIDTH];
// labels compacted to uint8 (100KB -> L1-resident alongside gather lines)
__device__ __align__(16) unsigned char g_labels8[N_CELLS_MAX];

// ---------------------------------------------------------------------------
// Kernel 1 (fused): heights build (warp per row) + label int32->uint8 pack.
// ---------------------------------------------------------------------------
__global__ void __launch_bounds__(256) build_kernel(
    const float* __restrict__ baseline,
    const float* __restrict__ delta,
    const int*   __restrict__ regions_oi,
    const int*   __restrict__ labels,
    int n_rows, int n_clusters, int rowBlocks, int n_cells)
{
    if ((int)blockIdx.x < rowBlocks) {
        const int warp = (int)blockIdx.x * 8 + ((int)threadIdx.x >> 5);
        if (warp >= n_rows) return;
        const int lane = threadIdx.x & 31;
        const int roi = warp / n_clusters;
        const int cl  = warp - roi * n_clusters;
        const int region = regions_oi[roi];

        const float4* __restrict__ b4 = (const float4*)(baseline + (long long)region * BINWIDTH);
        const float4* __restrict__ d4 = (const float4*)(delta + ((long long)region * n_clusters + cl) * BINWIDTH);

        float4 v[4];
        float m = -INFINITY;
        #pragma unroll
        for (int it = 0; it < 4; it++) {
            const int idx = lane + it * 32;
            if (idx < 125) {
                float4 a = b4[idx];
                float4 d = d4[idx];
                v[it].x = a.x + d.x; v[it].y = a.y + d.y;
                v[it].z = a.z + d.z; v[it].w = a.w + d.w;
                m = fmaxf(m, fmaxf(fmaxf(v[it].x, v[it].y), fmaxf(v[it].z, v[it].w)));
            }
        }
        #pragma unroll
        for (int o = 16; o > 0; o >>= 1)
            m = fmaxf(m, __shfl_xor_sync(0xffffffffu, m, o));

        float s = 0.0f;
        #pragma unroll
        for (int it = 0; it < 4; it++) {
            const int idx = lane + it * 32;
            if (idx < 125) {
                s += __expf(v[it].x - m) + __expf(v[it].y - m)
                   + __expf(v[it].z - m) + __expf(v[it].w - m);
            }
        }
        #pragma unroll
        for (int o = 16; o > 0; o >>= 1)
            s += __shfl_xor_sync(0xffffffffu, s, o);

        const float sub = m + __logf(s) + logf((float)BINSIZE);

        float4* __restrict__ o4 = (float4*)(g_heights + (long long)warp * BINWIDTH);
        #pragma unroll
        for (int it = 0; it < 4; it++) {
            const int idx = lane + it * 32;
            if (idx < 125) {
                float4 h;
                h.x = v[it].x - sub; h.y = v[it].y - sub;
                h.z = v[it].z - sub; h.w = v[it].w - sub;
                o4[idx] = h;
            }
        }
    } else {
        const int b = (int)blockIdx.x - rowBlocks;
        const int t = b * 256 + (int)threadIdx.x;
        const int i0 = t * 4;
        if (i0 + 4 <= n_cells) {
            const int4 l = ((const int4*)labels)[t];
            uchar4 p;
            p.x = (unsigned char)l.x; p.y = (unsigned char)l.y;
            p.z = (unsigned char)l.z; p.w = (unsigned char)l.w;
            ((uchar4*)g_labels8)[t] = p;
        } else {
            for (int i = i0; i < n_cells; i++)
                g_labels8[i] = (unsigned char)labels[i];
        }
    }
}

// ---------------------------------------------------------------------------
// Kernel 2: per-fragment gather, 4 fragments/thread (best measured config).
// Streaming traffic uses .cs (evict-first) so the label table (100KB) and
// hot heights lines stay cache-resident. No smem: full 228KB L1 carveout.
// ---------------------------------------------------------------------------
__global__ void __launch_bounds__(256) gather_kernel(
    const int*   __restrict__ coords,      // [n, 2]
    const int*   __restrict__ lrix,        // [n]
    const int*   __restrict__ lcix,        // [n]
    const float* __restrict__ inside,      // [1]
    float*       __restrict__ out,         // [n, 2]
    int n)
{
    const int g  = blockIdx.x * blockDim.x + threadIdx.x;
    const int i0 = g * 4;
    if (i0 >= n) return;

    const float x    = inside[0];
    const float l1p  = log1pf(expf(-x));
    const float lpIn  = -l1p     - logf((float)BINWIDTH);
    const float lpOut = -x - l1p - logf((float)(100000 - BINWIDTH));

    if (i0 + 4 <= n) {
        // streaming loads: evict-first, keep L1/L2 for the gather tables
        const int4 c0 = __ldcs((const int4*)coords + g * 2 + 0);
        const int4 c1 = __ldcs((const int4*)coords + g * 2 + 1);
        const int4 rr = __ldcs((const int4*)lrix + g);
        const int4 qq = __ldcs((const int4*)lcix + g);

        // label gathers (byte table, L1-resident)
        const int lab0 = __ldg(&g_labels8[qq.x]);
        const int lab1 = __ldg(&g_labels8[qq.y]);
        const int lab2 = __ldg(&g_labels8[qq.z]);
        const int lab3 = __ldg(&g_labels8[qq.w]);

        const int bl0 = c0.x / BINSIZE, br0 = c0.y / BINSIZE;
        const int bl1 = c0.z / BINSIZE, br1 = c0.w / BINSIZE;
        const int bl2 = c1.x / BINSIZE, br2 = c1.y / BINSIZE;
        const int bl3 = c1.z / BINSIZE, br3 = c1.w / BINSIZE;

        // heights gathers (8MB, L2-resident)
        const float L0 = __ldg(&g_heights[(rr.x * N_CLUSTERS + lab0) * BINWIDTH + bl0]);
        const float L1 = __ldg(&g_heights[(rr.y * N_CLUSTERS + lab1) * BINWIDTH + bl1]);
        const float L2 = __ldg(&g_heights[(rr.z * N_CLUSTERS + lab2) * BINWIDTH + bl2]);
        const float L3 = __ldg(&g_heights[(rr.w * N_CLUSTERS + lab3) * BINWIDTH + bl3]);

        float4 o0, o1;
        o0.x = L0; o0.y = (bl0 == br0) ? lpIn : lpOut;
        o0.z = L1; o0.w = (bl1 == br1) ? lpIn : lpOut;
        o1.x = L2; o1.y = (bl2 == br2) ? lpIn : lpOut;
        o1.z = L3; o1.w = (bl3 == br3) ? lpIn : lpOut;
        __stcs((float4*)out + g * 2 + 0, o0);
        __stcs((float4*)out + g * 2 + 1, o1);
    } else {
        for (int i = i0; i < n; i++) {
            const int cx = coords[i * 2 + 0];
            const int cy = coords[i * 2 + 1];
            const int bl = cx / BINSIZE, br = cy / BINSIZE;
            const int lab = g_labels8[lcix[i]];
            const int rg = lrix[i];
            out[i * 2 + 0] = g_heights[(rg * N_CLUSTERS + lab) * BINWIDTH + bl];
            out[i * 2 + 1] = (bl == br) ? lpIn : lpOut;
        }
    }
}

// ---------------------------------------------------------------------------
extern "C" void kernel_launch(void* const* d_in, const int* in_sizes, int n_in,
                              void* d_out, int out_size)
{
    const float* baseline = (const float*)d_in[0];
    const float* delta    = (const float*)d_in[1];
    const float* inside   = (const float*)d_in[2];
    const int*   regions  = (const int*)d_in[3];
    const int*   coords   = (const int*)d_in[4];
    const int*   lrix     = (const int*)d_in[5];
    const int*   lcix     = (const int*)d_in[6];
    const int*   labels   = (const int*)d_in[7];
    float*       out      = (float*)d_out;

    const int n_roi      = in_sizes[3];
    const int n          = in_sizes[5];
    const int n_cells    = in_sizes[7];
    const int n_regions  = in_sizes[0] / BINWIDTH;
    const int n_clusters = (n_regions > 0) ? (in_sizes[1] / (n_regions * BINWIDTH)) : N_CLUSTERS;

    const int n_rows    = n_roi * n_clusters;
    const int rowBlocks = (n_rows + 7) / 8;
    const int packBlocks = (n_cells + 1023) / 1024;
    build_kernel<<<rowBlocks + packBlocks, 256>>>(
        baseline, delta, regions, labels, n_rows, n_clusters, rowBlocks, n_cells);

    const int n_groups = (n + 3) / 4;
    const int blocks   = (n_groups + 255) / 256;
    gather_kernel<<<blocks, 256>>>(coords, lrix, lcix, inside, out, n);
}